// round 6
// baseline (speedup 1.0000x reference)
#include <cuda_runtime.h>
#include <cub/cub.cuh>
#include <math.h>

#define NEGF (-1000000000.0f)
#define TPI 218240
#define TALL 436480

__constant__ int dWl[5]={256,128,64,32,16};
__constant__ int dStr[5]={4,8,16,32,64};
__constant__ int dSz[5]={32,64,128,256,512};
__constant__ int dOff[5]={0,163840,204800,215040,217600};
__constant__ int dK[5]={6000,6000,6000,2560,640};
__constant__ double dRatio[4]={0.2323283,0.63365731,1.28478321,3.15089189};

__device__ float g_t[(size_t)2*256*40960];      // conv output (reused per level)
__device__ float g_wT[9*256*256];               // conv w transposed [tap][ic][oc]
__device__ float g_wh[256*20];                  // fused head weights [ic][20]
__device__ float g_hb[20];
__device__ float g_obj[TALL];
__device__ float g_reg[(size_t)TALL*4];
__device__ unsigned long long g_k0[TALL], g_k1[TALL];
__device__ unsigned g_v0[TALL], g_v1[TALL];
__device__ float g_tb[10*6000*4];               // decoded top-k boxes per (b,l)
__device__ float g_ts[10*6000];                 // scores (sigmoid)
__device__ float g_ta[10*6000];                 // areas
__device__ float g_ab[10000*4];                 // per-image concat boxes (5000 x 2)
__device__ float g_as[10000];
__device__ unsigned long long g_f0[10000], g_f1[10000];
__device__ unsigned g_fv0[10000], g_fv1[10000];
__device__ __align__(256) unsigned char g_tmp[32u*1024u*1024u];

__device__ __forceinline__ unsigned sortable_f32(float f){
    unsigned u=__float_as_uint(f);
    return (u&0x80000000u)?~u:(u|0x80000000u);
}
__device__ __forceinline__ unsigned long long pk2(float x,float y){
    unsigned long long r;
    asm("mov.b64 %0,{%1,%2};":"=l"(r):"r"(__float_as_uint(x)),"r"(__float_as_uint(y)));
    return r;
}
__device__ __forceinline__ void fma2(unsigned long long&d,unsigned long long a,unsigned long long b){
    asm("fma.rn.f32x2 %0,%1,%2,%0;":"+l"(d):"l"(a),"l"(b));
}
__device__ __forceinline__ float2 up2(unsigned long long v){
    unsigned lo,hi; asm("mov.b64 {%0,%1},%2;":"=r"(lo),"=r"(hi):"l"(v));
    return make_float2(__uint_as_float(lo),__uint_as_float(hi));
}

// ---------- prep: transpose conv weights, fuse 1x1 head weights ----------
__global__ void prep_k(const float* __restrict__ cw,const float* __restrict__ clsw,
                       const float* __restrict__ bbw,const float* __restrict__ clsb,
                       const float* __restrict__ bbb){
    int i=blockIdx.x*blockDim.x+threadIdx.x;
    if(i<9*256*256){
        int tap=i/65536, r=i-tap*65536, ic=r>>8, oc=r&255;
        g_wT[i]=cw[(oc*256+ic)*9+tap];
    }
    if(i<256*20){
        int ic=i/20, o=i-ic*20;
        g_wh[i]=(o<4)?clsw[o*256+ic]:bbw[(o-4)*256+ic];
    }
    if(i<20) g_hb[i]=(i<4)?clsb[i]:bbb[i-4];
}

// ---------- conv3x3+bias+ReLU: 128oc x 128px tile, 8x8/thread, f32x2 FMA ----------
__global__ void __launch_bounds__(256,2) conv_k(const float* __restrict__ in,
        const float* __restrict__ bias,int H,int W){
    const int HW=H*W;
    const int tileP=blockIdx.x*128, ocB=blockIdx.y*128, b=blockIdx.z;
    const float* __restrict__ inB=in+(size_t)b*256*HW;
    float* __restrict__ outB=g_t+(size_t)b*256*HW;
    __shared__ float As[2][8][128];
    __shared__ float Bs[2][8][128];
    __shared__ int sIdx[9][128];
    const int tid=threadIdx.x, tx=tid&15, ty=tid>>4;

    for(int idx=tid;idx<9*128;idx+=256){
        int tap=idx>>7, p=idx&127, g=tileP+p, s=-1;
        if(g<HW){
            int y=g/W, x=g-y*W;
            int yy=y+tap/3-1, xx=x+(tap-(tap/3)*3)-1;
            if(yy>=0&&yy<H&&xx>=0&&xx<W) s=yy*W+xx;
        }
        sIdx[tap][p]=s;
    }
    __syncthreads();

    unsigned long long acc[8][4];
#pragma unroll
    for(int i=0;i<8;i++)
#pragma unroll
        for(int j=0;j<4;j++) acc[i][j]=0ull;

    float ra[4],rb[4];
    {
        const int* sI=sIdx[0];
#pragma unroll
        for(int j=0;j<4;j++){
            int idx=tid+(j<<8), k=idx>>7, q=idx&127;
            ra[j]=g_wT[(size_t)k*256+ocB+q];
            int s=sI[q]; rb[j]=(s>=0)?inB[(size_t)k*HW+s]:0.f;
        }
#pragma unroll
        for(int j=0;j<4;j++){
            int idx=tid+(j<<8), k=idx>>7, q=idx&127;
            As[0][k][q]=ra[j]; Bs[0][k][q]=rb[j];
        }
        __syncthreads();
    }

    for(int c=0;c<288;c++){
        int buf=c&1; bool pf=(c+1<288);
        if(pf){
            int cn=c+1, tap=cn>>5, icc=(cn&31)<<3;
            const int* sI=sIdx[tap];
#pragma unroll
            for(int j=0;j<4;j++){
                int idx=tid+(j<<8), k=idx>>7, q=idx&127;
                ra[j]=g_wT[((size_t)(tap<<8)+icc+k)*256+ocB+q];
                int s=sI[q]; rb[j]=(s>=0)?inB[(size_t)(icc+k)*HW+s]:0.f;
            }
        }
#pragma unroll
        for(int k=0;k<8;k++){
            float4 a0=*(const float4*)&As[buf][k][ty*4];
            float4 a1=*(const float4*)&As[buf][k][64+ty*4];
            float4 b0=*(const float4*)&Bs[buf][k][tx*4];
            float4 b1=*(const float4*)&Bs[buf][k][64+tx*4];
            unsigned long long bv[4];
            bv[0]=pk2(b0.x,b0.y); bv[1]=pk2(b0.z,b0.w);
            bv[2]=pk2(b1.x,b1.y); bv[3]=pk2(b1.z,b1.w);
            float av[8]={a0.x,a0.y,a0.z,a0.w,a1.x,a1.y,a1.z,a1.w};
#pragma unroll
            for(int i=0;i<8;i++){
                unsigned long long ai=pk2(av[i],av[i]);
#pragma unroll
                for(int j=0;j<4;j++) fma2(acc[i][j],ai,bv[j]);
            }
        }
        if(pf){
            int nb=buf^1;
#pragma unroll
            for(int j=0;j<4;j++){
                int idx=tid+(j<<8), k=idx>>7, q=idx&127;
                As[nb][k][q]=ra[j]; Bs[nb][k][q]=rb[j];
            }
        }
        __syncthreads();
    }

#pragma unroll
    for(int i=0;i<8;i++){
        int oc=ocB+((i<4)?(ty*4+i):(64+ty*4+i-4));
        float bv=bias[oc];
        float* row=outB+(size_t)oc*HW;
        float2 v0=up2(acc[i][0]), v1=up2(acc[i][1]);
        float2 v2=up2(acc[i][2]), v3=up2(acc[i][3]);
        int p0=tileP+tx*4;
        if(p0<HW){
            float4 v; v.x=fmaxf(v0.x+bv,0.f); v.y=fmaxf(v0.y+bv,0.f);
            v.z=fmaxf(v1.x+bv,0.f); v.w=fmaxf(v1.y+bv,0.f);
            *(float4*)&row[p0]=v;
        }
        int p1=tileP+64+tx*4;
        if(p1<HW){
            float4 v; v.x=fmaxf(v2.x+bv,0.f); v.y=fmaxf(v2.y+bv,0.f);
            v.z=fmaxf(v3.x+bv,0.f); v.w=fmaxf(v3.y+bv,0.f);
            *(float4*)&row[p1]=v;
        }
    }
}

// ---------- fused 1x1 heads + sort-key emission ----------
__global__ void head_k(int HW,int lvl){
    __shared__ float ws[256*20];
    __shared__ float wb[20];
    int tid=threadIdx.x;
    for(int i=tid;i<5120;i+=128) ws[i]=g_wh[i];
    if(tid<20) wb[tid]=g_hb[tid];
    __syncthreads();
    int px=blockIdx.x*128+tid;
    int b=blockIdx.z;
    if(px>=HW) return;
    const float* tb=g_t+(size_t)b*256*HW+px;
    float acc[20];
#pragma unroll
    for(int o=0;o<20;o++) acc[o]=wb[o];
#pragma unroll 4
    for(int ic=0;ic<256;ic++){
        float x=__ldg(&tb[(size_t)ic*HW]);
        const float* w=&ws[ic*20];
#pragma unroll
        for(int o=0;o<20;o++) acc[o]+=x*w[o];
    }
    size_t base=(size_t)b*TPI+dOff[lvl]+(size_t)px*4;
    int seg=b*5+lvl;
#pragma unroll
    for(int a=0;a<4;a++){
        float lg=acc[a];
        g_obj[base+a]=lg;
        unsigned u=sortable_f32(lg);
        g_k0[base+a]=((unsigned long long)seg<<32)|(unsigned long long)(unsigned)(~u);
        g_v0[base+a]=(unsigned)(px*4+a);
#pragma unroll
        for(int cc=0;cc<4;cc++) g_reg[(base+a)*4+cc]=acc[4+a*4+cc];
    }
}

// ---------- per-(b,l) top-k decode + clip (bit-faithful elementwise) ----------
__global__ void decode_k(const int* __restrict__ ihp,const int* __restrict__ iwp){
    int id=blockIdx.x*blockDim.x+threadIdx.x;
    if(id>=60000) return;
    int s=id/6000, i=id-s*6000, b=s/5, l=s-b*5;
    if(i>=dK[l]) return;
    size_t base=(size_t)b*TPI+dOff[l];
    unsigned n=g_v1[base+i];
    int a=n&3, p=n>>2, W=dWl[l], y=p/W, x=p-y*W;
    double sz=(double)dSz[l], rt=dRatio[a];
    double wsd=sqrt(sz*sz/rt), hsd=wsd*rt;
    double gx=(double)(x*dStr[l]), gy=(double)(y*dStr[l]);
    float a0=(float)(gx-wsd*0.5), a1=(float)(gy-hsd*0.5);
    float a2=(float)(gx+wsd*0.5), a3=(float)(gy+hsd*0.5);
    const float* r=&g_reg[(base+n)*4];
    float dx=r[0],dy=r[1];
    float dw=fminf(r[2],4.135166556742356f), dh=fminf(r[3],4.135166556742356f);
    float wa=__fadd_rn(__fsub_rn(a2,a0),1.f), ha=__fadd_rn(__fsub_rn(a3,a1),1.f);
    float cxa=__fadd_rn(a0,__fmul_rn(0.5f,wa)), cya=__fadd_rn(a1,__fmul_rn(0.5f,ha));
    float cx=__fadd_rn(__fmul_rn(dx,wa),cxa), cy=__fadd_rn(__fmul_rn(dy,ha),cya);
    float w=__fmul_rn((float)exp((double)dw),wa), h=__fmul_rn((float)exp((double)dh),ha);
    float x1=__fsub_rn(cx,__fmul_rn(0.5f,w)), y1=__fsub_rn(cy,__fmul_rn(0.5f,h));
    float x2=__fsub_rn(__fadd_rn(cx,__fmul_rn(0.5f,w)),1.f);
    float y2=__fsub_rn(__fadd_rn(cy,__fmul_rn(0.5f,h)),1.f);
    float mw=(float)(*iwp)-1.f, mh=(float)(*ihp)-1.f;
    x1=fminf(fmaxf(x1,0.f),mw); x2=fminf(fmaxf(x2,0.f),mw);
    y1=fminf(fmaxf(y1,0.f),mh); y2=fminf(fmaxf(y2,0.f),mh);
    float* ob=&g_tb[(size_t)(s*6000+i)*4];
    ob[0]=x1; ob[1]=y1; ob[2]=x2; ob[3]=y2;
    g_ta[s*6000+i]=__fmul_rn(__fsub_rn(x2,x1),__fsub_rn(y2,y1));
    float lg=g_obj[base+n];
    g_ts[s*6000+i]=(float)(1.0/(1.0+exp(-(double)lg)));
}

// ---------- greedy NMS (== reference argmax-scan on sorted scores) ----------
__global__ void nms_k(){
    int s=blockIdx.x, b=s/5, l=s-b*5;
    int k=dK[l], n_out=min(1000,k);
    __shared__ unsigned char sup[6000];
    __shared__ int keep[1000];
    __shared__ int sBi;
    __shared__ float sB[5];
    int tid=threadIdx.x;
    for(int j=tid;j<6000;j+=256) sup[j]=0;
    for(int j=tid;j<1000;j+=256) keep[j]=-1;
    const float* bx=&g_tb[(size_t)s*6000*4];
    const float* ar=&g_ta[s*6000];
    __syncthreads();
    int cur=0;
    for(int kept=0;kept<n_out;kept++){
        if(tid==0){
            while(cur<k && sup[cur]) cur++;
            if(cur<k){
                sBi=cur; keep[kept]=cur;
                sB[0]=bx[cur*4]; sB[1]=bx[cur*4+1];
                sB[2]=bx[cur*4+2]; sB[3]=bx[cur*4+3]; sB[4]=ar[cur];
                cur++;
            } else sBi=-1;
        }
        __syncthreads();
        if(sBi<0) break;
        float b0=sB[0],b1=sB[1],b2=sB[2],b3=sB[3],ba=sB[4];
        for(int j=tid;j<k;j+=256){
            if(sup[j]) continue;
            float xx1=fmaxf(b0,bx[j*4]), yy1=fmaxf(b1,bx[j*4+1]);
            float xx2=fminf(b2,bx[j*4+2]), yy2=fminf(b3,bx[j*4+3]);
            float inter=__fmul_rn(fmaxf(__fsub_rn(xx2,xx1),0.f),
                                  fmaxf(__fsub_rn(yy2,yy1),0.f));
            float den=__fadd_rn(__fsub_rn(__fadd_rn(ba,ar[j]),inter),1e-9f);
            if(__fdiv_rn(inter,den)>0.7f) sup[j]=1;
        }
        __syncthreads();
    }
    __syncthreads();
    for(int j=tid;j<1000;j+=256){
        int gi=b*5000+l*1000+j;
        float B0=0.f,B1=0.f,B2=0.f,B3=0.f,S=NEGF;
        if(j<n_out){
            int ki=keep[j];
            if(ki>=0){
                B0=bx[ki*4];B1=bx[ki*4+1];B2=bx[ki*4+2];B3=bx[ki*4+3];
                S=g_ts[s*6000+ki];
            } else { B0=bx[0];B1=bx[1];B2=bx[2];B3=bx[3]; S=NEGF; }
        }
        g_ab[(size_t)gi*4]=B0; g_ab[(size_t)gi*4+1]=B1;
        g_ab[(size_t)gi*4+2]=B2; g_ab[(size_t)gi*4+3]=B3;
        g_as[gi]=S;
        unsigned u=sortable_f32(S);
        g_f0[gi]=((unsigned long long)b<<32)|(unsigned long long)(unsigned)(~u);
        g_fv0[gi]=(unsigned)(l*1000+j);
    }
}

// ---------- final gather ----------
__global__ void out_k(float* __restrict__ out){
    int id=blockIdx.x*blockDim.x+threadIdx.x;
    if(id>=2000) return;
    int b=id/1000, r=id-b*1000;
    unsigned idx=g_fv1[b*5000+r];
    float* o=&out[(size_t)(b*1000+r)*5];
    const float* bb=&g_ab[((size_t)b*5000+idx)*4];
    o[0]=bb[0]; o[1]=bb[1]; o[2]=bb[2]; o[3]=bb[3];
    o[4]=g_as[b*5000+idx];
}

extern "C" void kernel_launch(void* const* d_in,const int* in_sizes,int n_in,
                              void* d_out,int out_size){
    const float* feats[5]={(const float*)d_in[0],(const float*)d_in[1],
                           (const float*)d_in[2],(const float*)d_in[3],
                           (const float*)d_in[4]};
    const float* conv_w=(const float*)d_in[5];
    const float* conv_b=(const float*)d_in[6];
    const float* cls_w =(const float*)d_in[7];
    const float* cls_b =(const float*)d_in[8];
    const float* bbox_w=(const float*)d_in[9];
    const float* bbox_b=(const float*)d_in[10];
    const int* ih=(const int*)d_in[11];
    const int* iw=(const int*)d_in[12];

    prep_k<<<2304,256>>>(conv_w,cls_w,bbox_w,cls_b,bbox_b);

    static const int Hl[5]={160,80,40,20,10};
    static const int Wl[5]={256,128,64,32,16};
    for(int l=0;l<5;l++){
        int H=Hl[l],W=Wl[l],HW=H*W;
        conv_k<<<dim3((HW+127)/128,2,2),256>>>(feats[l],conv_b,H,W);
        head_k<<<dim3((HW+127)/128,1,2),128>>>(HW,l);
    }

    void *pk0,*pk1,*pv0,*pv1,*pt,*pf0,*pf1,*pfv0,*pfv1;
    cudaGetSymbolAddress(&pk0,g_k0);  cudaGetSymbolAddress(&pk1,g_k1);
    cudaGetSymbolAddress(&pv0,g_v0);  cudaGetSymbolAddress(&pv1,g_v1);
    cudaGetSymbolAddress(&pt,g_tmp);
    cudaGetSymbolAddress(&pf0,g_f0);  cudaGetSymbolAddress(&pf1,g_f1);
    cudaGetSymbolAddress(&pfv0,g_fv0); cudaGetSymbolAddress(&pfv1,g_fv1);

    size_t tb=0;
    cub::DeviceRadixSort::SortPairs(nullptr,tb,
        (const unsigned long long*)pk0,(unsigned long long*)pk1,
        (const unsigned*)pv0,(unsigned*)pv1,TALL,0,36);
    if(tb>sizeof(g_tmp)) return;
    size_t tcap=sizeof(g_tmp);
    cub::DeviceRadixSort::SortPairs(pt,tcap,
        (const unsigned long long*)pk0,(unsigned long long*)pk1,
        (const unsigned*)pv0,(unsigned*)pv1,TALL,0,36);

    decode_k<<<(60000+255)/256,256>>>(ih,iw);
    nms_k<<<10,256>>>();

    size_t tcap2=sizeof(g_tmp);
    cub::DeviceRadixSort::SortPairs(pt,tcap2,
        (const unsigned long long*)pf0,(unsigned long long*)pf1,
        (const unsigned*)pfv0,(unsigned*)pfv1,10000,0,33);

    out_k<<<8,256>>>((float*)d_out);
}

// round 8
// speedup vs baseline: 1.9468x; 1.9468x over previous
#include <cuda_runtime.h>
#include <cub/cub.cuh>
#include <math.h>

#define NEGF (-1000000000.0f)
#define TPI 218240
#define TALL 436480
#define MAXW 94

__constant__ int dWl[5]={256,128,64,32,16};
__constant__ int dStr[5]={4,8,16,32,64};
__constant__ int dSz[5]={32,64,128,256,512};
__constant__ int dOff[5]={0,163840,204800,215040,217600};
__constant__ int dK[5]={6000,6000,6000,2560,640};
__constant__ double dRatio[4]={0.2323283,0.63365731,1.28478321,3.15089189};

__device__ float g_t[(size_t)2*256*40960];      // conv output (reused per level)
__device__ unsigned long long g_wT2[9*256*256]; // conv w transposed+dup [tap][ic][oc]->(w,w)
__device__ float g_wh[256*20];                  // fused head weights [ic][20]
__device__ float g_hb[20];
__device__ float g_obj[TALL];
__device__ float g_reg[(size_t)TALL*4];
__device__ unsigned long long g_k0[TALL], g_k1[TALL];
__device__ unsigned g_v0[TALL], g_v1[TALL];
__device__ float g_tb[10*6000*4];               // decoded top-k boxes per (b,l)
__device__ float g_ts[10*6000];                 // scores (sigmoid)
__device__ float g_ta[10*6000];                 // areas
__device__ unsigned long long g_mask[(size_t)10*6000*MAXW]; // NMS suppression bitmap
__device__ float g_ab[10000*4];                 // per-image concat boxes (5000 x 2)
__device__ float g_as[10000];
__device__ unsigned long long g_f0[10000], g_f1[10000];
__device__ unsigned g_fv0[10000], g_fv1[10000];
__device__ __align__(256) unsigned char g_tmp[32u*1024u*1024u];

__device__ __forceinline__ unsigned sortable_f32(float f){
    unsigned u=__float_as_uint(f);
    return (u&0x80000000u)?~u:(u|0x80000000u);
}
__device__ __forceinline__ unsigned long long pk2(float x,float y){
    unsigned long long r;
    asm("mov.b64 %0,{%1,%2};":"=l"(r):"r"(__float_as_uint(x)),"r"(__float_as_uint(y)));
    return r;
}
__device__ __forceinline__ void fma2(unsigned long long&d,unsigned long long a,unsigned long long b){
    asm("fma.rn.f32x2 %0,%1,%2,%0;":"+l"(d):"l"(a),"l"(b));
}
__device__ __forceinline__ float2 up2(unsigned long long v){
    unsigned lo,hi; asm("mov.b64 {%0,%1},%2;":"=r"(lo),"=r"(hi):"l"(v));
    return make_float2(__uint_as_float(lo),__uint_as_float(hi));
}

// ---------- prep: transpose+duplicate conv weights, fuse 1x1 head weights ----------
__global__ void prep_k(const float* __restrict__ cw,const float* __restrict__ clsw,
                       const float* __restrict__ bbw,const float* __restrict__ clsb,
                       const float* __restrict__ bbb){
    int i=blockIdx.x*blockDim.x+threadIdx.x;
    if(i<9*256*256){
        int tap=i/65536, r=i-tap*65536, ic=r>>8, oc=r&255;
        float w=cw[(oc*256+ic)*9+tap];
        g_wT2[i]=pk2(w,w);
    }
    if(i<256*20){
        int ic=i/20, o=i-ic*20;
        g_wh[i]=(o<4)?clsw[o*256+ic]:bbw[(o-4)*256+ic];
    }
    if(i<20) g_hb[i]=(i<4)?clsb[i]:bbb[i-4];
}

// ---------- conv3x3+bias+ReLU: 128oc x 128px tile, 8x8/thread, f32x2 FMA ----------
// Weights pre-duplicated -> inner loop is 6xLDS.128 + 32xFFMA2 per k-step.
__global__ void __launch_bounds__(256,2) conv_k(const float* __restrict__ in,
        const float* __restrict__ bias,int H,int W){
    const int HW=H*W;
    const int tileP=blockIdx.x*128, ocB=blockIdx.y*128, b=blockIdx.z;
    const float* __restrict__ inB=in+(size_t)b*256*HW;
    float* __restrict__ outB=g_t+(size_t)b*256*HW;
    __shared__ unsigned long long Asu[2][8][128];
    __shared__ float Bs[2][8][128];
    __shared__ int sIdx[9][128];
    const int tid=threadIdx.x, tx=tid&15, ty=tid>>4;

    for(int idx=tid;idx<9*128;idx+=256){
        int tap=idx>>7, p=idx&127, g=tileP+p, s=-1;
        if(g<HW){
            int y=g/W, x=g-y*W;
            int yy=y+tap/3-1, xx=x+(tap-(tap/3)*3)-1;
            if(yy>=0&&yy<H&&xx>=0&&xx<W) s=yy*W+xx;
        }
        sIdx[tap][p]=s;
    }
    __syncthreads();

    unsigned long long acc[8][4];
#pragma unroll
    for(int i=0;i<8;i++)
#pragma unroll
        for(int j=0;j<4;j++) acc[i][j]=0ull;

    unsigned long long ra[4]; float rb[4];
    {
        const int* sI=sIdx[0];
#pragma unroll
        for(int j=0;j<4;j++){
            int idx=tid+(j<<8), k=idx>>7, q=idx&127;
            ra[j]=g_wT2[(size_t)k*256+ocB+q];
            int s=sI[q]; rb[j]=(s>=0)?inB[(size_t)k*HW+s]:0.f;
        }
#pragma unroll
        for(int j=0;j<4;j++){
            int idx=tid+(j<<8), k=idx>>7, q=idx&127;
            Asu[0][k][q]=ra[j]; Bs[0][k][q]=rb[j];
        }
        __syncthreads();
    }

    for(int c=0;c<288;c++){
        int buf=c&1; bool pf=(c+1<288);
        if(pf){
            int cn=c+1, tap=cn>>5, icc=(cn&31)<<3;
            const int* sI=sIdx[tap];
#pragma unroll
            for(int j=0;j<4;j++){
                int idx=tid+(j<<8), k=idx>>7, q=idx&127;
                ra[j]=g_wT2[((size_t)(tap<<8)+icc+k)*256+ocB+q];
                int s=sI[q]; rb[j]=(s>=0)?inB[(size_t)(icc+k)*HW+s]:0.f;
            }
        }
#pragma unroll
        for(int k=0;k<8;k++){
            ulonglong2 a0=*(const ulonglong2*)&Asu[buf][k][ty*4];
            ulonglong2 a1=*(const ulonglong2*)&Asu[buf][k][ty*4+2];
            ulonglong2 a2=*(const ulonglong2*)&Asu[buf][k][64+ty*4];
            ulonglong2 a3=*(const ulonglong2*)&Asu[buf][k][64+ty*4+2];
            ulonglong2 bq0=*(const ulonglong2*)&Bs[buf][k][tx*4];
            ulonglong2 bq1=*(const ulonglong2*)&Bs[buf][k][64+tx*4];
            unsigned long long av[8]={a0.x,a0.y,a1.x,a1.y,a2.x,a2.y,a3.x,a3.y};
            unsigned long long bv[4]={bq0.x,bq0.y,bq1.x,bq1.y};
#pragma unroll
            for(int i=0;i<8;i++)
#pragma unroll
                for(int j=0;j<4;j++) fma2(acc[i][j],av[i],bv[j]);
        }
        if(pf){
            int nb=buf^1;
#pragma unroll
            for(int j=0;j<4;j++){
                int idx=tid+(j<<8), k=idx>>7, q=idx&127;
                Asu[nb][k][q]=ra[j]; Bs[nb][k][q]=rb[j];
            }
        }
        __syncthreads();
    }

#pragma unroll
    for(int i=0;i<8;i++){
        int oc=ocB+((i<4)?(ty*4+i):(64+ty*4+i-4));
        float bv=bias[oc];
        float* row=outB+(size_t)oc*HW;
        float2 v0=up2(acc[i][0]), v1=up2(acc[i][1]);
        float2 v2=up2(acc[i][2]), v3=up2(acc[i][3]);
        int p0=tileP+tx*4;
        if(p0<HW){
            float4 v; v.x=fmaxf(v0.x+bv,0.f); v.y=fmaxf(v0.y+bv,0.f);
            v.z=fmaxf(v1.x+bv,0.f); v.w=fmaxf(v1.y+bv,0.f);
            *(float4*)&row[p0]=v;
        }
        int p1=tileP+64+tx*4;
        if(p1<HW){
            float4 v; v.x=fmaxf(v2.x+bv,0.f); v.y=fmaxf(v2.y+bv,0.f);
            v.z=fmaxf(v3.x+bv,0.f); v.w=fmaxf(v3.y+bv,0.f);
            *(float4*)&row[p1]=v;
        }
    }
}

// ---------- fused 1x1 heads + sort-key emission ----------
__global__ void head_k(int HW,int lvl){
    __shared__ float ws[256*20];
    __shared__ float wb[20];
    int tid=threadIdx.x;
    for(int i=tid;i<5120;i+=128) ws[i]=g_wh[i];
    if(tid<20) wb[tid]=g_hb[tid];
    __syncthreads();
    int px=blockIdx.x*128+tid;
    int b=blockIdx.z;
    if(px>=HW) return;
    const float* tb=g_t+(size_t)b*256*HW+px;
    float acc[20];
#pragma unroll
    for(int o=0;o<20;o++) acc[o]=wb[o];
#pragma unroll 4
    for(int ic=0;ic<256;ic++){
        float x=__ldg(&tb[(size_t)ic*HW]);
        const float* w=&ws[ic*20];
#pragma unroll
        for(int o=0;o<20;o++) acc[o]+=x*w[o];
    }
    size_t base=(size_t)b*TPI+dOff[lvl]+(size_t)px*4;
    int seg=b*5+lvl;
#pragma unroll
    for(int a=0;a<4;a++){
        float lg=acc[a];
        g_obj[base+a]=lg;
        unsigned u=sortable_f32(lg);
        g_k0[base+a]=((unsigned long long)seg<<32)|(unsigned long long)(unsigned)(~u);
        g_v0[base+a]=(unsigned)(px*4+a);
#pragma unroll
        for(int cc=0;cc<4;cc++) g_reg[(base+a)*4+cc]=acc[4+a*4+cc];
    }
}

// ---------- per-(b,l) top-k decode + clip (bit-faithful elementwise) ----------
__global__ void decode_k(const int* __restrict__ ihp,const int* __restrict__ iwp){
    int id=blockIdx.x*blockDim.x+threadIdx.x;
    if(id>=60000) return;
    int s=id/6000, i=id-s*6000, b=s/5, l=s-b*5;
    if(i>=dK[l]) return;
    size_t base=(size_t)b*TPI+dOff[l];
    unsigned n=g_v1[base+i];
    int a=n&3, p=n>>2, W=dWl[l], y=p/W, x=p-y*W;
    double sz=(double)dSz[l], rt=dRatio[a];
    double wsd=sqrt(sz*sz/rt), hsd=wsd*rt;
    double gx=(double)(x*dStr[l]), gy=(double)(y*dStr[l]);
    float a0=(float)(gx-wsd*0.5), a1=(float)(gy-hsd*0.5);
    float a2=(float)(gx+wsd*0.5), a3=(float)(gy+hsd*0.5);
    const float* r=&g_reg[(base+n)*4];
    float dx=r[0],dy=r[1];
    float dw=fminf(r[2],4.135166556742356f), dh=fminf(r[3],4.135166556742356f);
    float wa=__fadd_rn(__fsub_rn(a2,a0),1.f), ha=__fadd_rn(__fsub_rn(a3,a1),1.f);
    float cxa=__fadd_rn(a0,__fmul_rn(0.5f,wa)), cya=__fadd_rn(a1,__fmul_rn(0.5f,ha));
    float cx=__fadd_rn(__fmul_rn(dx,wa),cxa), cy=__fadd_rn(__fmul_rn(dy,ha),cya);
    float w=__fmul_rn((float)exp((double)dw),wa), h=__fmul_rn((float)exp((double)dh),ha);
    float x1=__fsub_rn(cx,__fmul_rn(0.5f,w)), y1=__fsub_rn(cy,__fmul_rn(0.5f,h));
    float x2=__fsub_rn(__fadd_rn(cx,__fmul_rn(0.5f,w)),1.f);
    float y2=__fsub_rn(__fadd_rn(cy,__fmul_rn(0.5f,h)),1.f);
    float mw=(float)(*iwp)-1.f, mh=(float)(*ihp)-1.f;
    x1=fminf(fmaxf(x1,0.f),mw); x2=fminf(fmaxf(x2,0.f),mw);
    y1=fminf(fmaxf(y1,0.f),mh); y2=fminf(fmaxf(y2,0.f),mh);
    float* ob=&g_tb[(size_t)(s*6000+i)*4];
    ob[0]=x1; ob[1]=y1; ob[2]=x2; ob[3]=y2;
    g_ta[s*6000+i]=__fmul_rn(__fsub_rn(x2,x1),__fsub_rn(y2,y1));
    float lg=g_obj[base+n];
    g_ts[s*6000+i]=(float)(1.0/(1.0+exp(-(double)lg)));
}

// ---------- NMS phase 1: pairwise suppression bitmap (fully parallel) ----------
// word (i, colB): bit t set iff j=colB*64+t, j>i, IoU(i,j) > 0.7 with the exact
// float op sequence of the reference. Only colB >= rowB blocks are written/read.
__global__ void mask_k(){
    int s=blockIdx.z;
    int rowB=blockIdx.y, colB=blockIdx.x;
    int l=s%5; int k=dK[l];
    if(rowB*64>=k || colB<rowB || colB*64>=k) return;
    __shared__ float cb[64*5];
    int tid=threadIdx.x;   // 64
    const float* bx=&g_tb[(size_t)s*6000*4];
    const float* ar=&g_ta[(size_t)s*6000];
    int j0=colB*64;
    if(j0+tid<k){
        cb[tid*5+0]=bx[(j0+tid)*4+0];
        cb[tid*5+1]=bx[(j0+tid)*4+1];
        cb[tid*5+2]=bx[(j0+tid)*4+2];
        cb[tid*5+3]=bx[(j0+tid)*4+3];
        cb[tid*5+4]=ar[j0+tid];
    }
    __syncthreads();
    int i=rowB*64+tid;
    if(i>=k) return;
    float b0=bx[i*4],b1=bx[i*4+1],b2=bx[i*4+2],b3=bx[i*4+3],ba=ar[i];
    unsigned long long m=0;
    int jmax=min(64,k-j0);
    for(int t=0;t<jmax;t++){
        int j=j0+t;
        if(j<=i) continue;
        float xx1=fmaxf(b0,cb[t*5+0]), yy1=fmaxf(b1,cb[t*5+1]);
        float xx2=fminf(b2,cb[t*5+2]), yy2=fminf(b3,cb[t*5+3]);
        float inter=__fmul_rn(fmaxf(__fsub_rn(xx2,xx1),0.f),
                              fmaxf(__fsub_rn(yy2,yy1),0.f));
        float den=__fadd_rn(__fsub_rn(__fadd_rn(ba,cb[t*5+4]),inter),1e-9f);
        if(__fdiv_rn(inter,den)>0.7f) m|=(1ull<<t);
    }
    g_mask[((size_t)s*6000+i)*MAXW+colB]=m;
}

// ---------- NMS phase 2: 1-warp greedy scan + output (== reference argmax scan) ----------
__global__ void scan_k(){
    int s=blockIdx.x; int b=s/5, l=s-b*5;
    int k=dK[l], n_out=min(1000,k);
    __shared__ int keep[1000];
    int tid=threadIdx.x;   // 128
    for(int j=tid;j<1000;j+=128) keep[j]=-1;
    __syncthreads();
    if(tid<32){
        unsigned long long rem0=0,rem1=0,rem2=0;
        const unsigned long long* MR=&g_mask[(size_t)s*6000*MAXW];
        int nw=(k+63)>>6;
        int nk=0;
        for(int i=0;i<k && nk<n_out;i++){
            int w=i>>6, slot=w>>5, lane=w&31;
            unsigned long long v=(slot==0)?rem0:((slot==1)?rem1:rem2);
            unsigned long long rw=__shfl_sync(0xffffffffu,v,lane);
            if((rw>>(i&63))&1ull) continue;
            if(tid==0) keep[nk]=i;
            nk++;
            const unsigned long long* row=MR+(size_t)i*MAXW;
            int w0=tid, w1=tid+32, w2=tid+64;
            if(w0<nw && w0>=w) rem0|=row[w0];
            if(w1<nw && w1>=w) rem1|=row[w1];
            if(w2<nw && w2>=w) rem2|=row[w2];
        }
    }
    __syncthreads();
    const float* bx=&g_tb[(size_t)s*6000*4];
    for(int j=tid;j<1000;j+=128){
        int gi=b*5000+l*1000+j;
        float B0=0.f,B1=0.f,B2=0.f,B3=0.f,S=NEGF;
        if(j<n_out){
            int ki=keep[j];
            if(ki>=0){
                B0=bx[ki*4];B1=bx[ki*4+1];B2=bx[ki*4+2];B3=bx[ki*4+3];
                S=g_ts[s*6000+ki];
            } else { B0=bx[0];B1=bx[1];B2=bx[2];B3=bx[3]; S=NEGF; }
        }
        g_ab[(size_t)gi*4]=B0; g_ab[(size_t)gi*4+1]=B1;
        g_ab[(size_t)gi*4+2]=B2; g_ab[(size_t)gi*4+3]=B3;
        g_as[gi]=S;
        unsigned u=sortable_f32(S);
        g_f0[gi]=((unsigned long long)b<<32)|(unsigned long long)(unsigned)(~u);
        g_fv0[gi]=(unsigned)(l*1000+j);
    }
}

// ---------- final gather ----------
__global__ void out_k(float* __restrict__ out){
    int id=blockIdx.x*blockDim.x+threadIdx.x;
    if(id>=2000) return;
    int b=id/1000, r=id-b*1000;
    unsigned idx=g_fv1[b*5000+r];
    float* o=&out[(size_t)(b*1000+r)*5];
    const float* bb=&g_ab[((size_t)b*5000+idx)*4];
    o[0]=bb[0]; o[1]=bb[1]; o[2]=bb[2]; o[3]=bb[3];
    o[4]=g_as[b*5000+idx];
}

extern "C" void kernel_launch(void* const* d_in,const int* in_sizes,int n_in,
                              void* d_out,int out_size){
    const float* feats[5]={(const float*)d_in[0],(const float*)d_in[1],
                           (const float*)d_in[2],(const float*)d_in[3],
                           (const float*)d_in[4]};
    const float* conv_w=(const float*)d_in[5];
    const float* conv_b=(const float*)d_in[6];
    const float* cls_w =(const float*)d_in[7];
    const float* cls_b =(const float*)d_in[8];
    const float* bbox_w=(const float*)d_in[9];
    const float* bbox_b=(const float*)d_in[10];
    const int* ih=(const int*)d_in[11];
    const int* iw=(const int*)d_in[12];

    prep_k<<<2304,256>>>(conv_w,cls_w,bbox_w,cls_b,bbox_b);

    static const int Hl[5]={160,80,40,20,10};
    static const int Wl[5]={256,128,64,32,16};
    for(int l=0;l<5;l++){
        int H=Hl[l],W=Wl[l],HW=H*W;
        conv_k<<<dim3((HW+127)/128,2,2),256>>>(feats[l],conv_b,H,W);
        head_k<<<dim3((HW+127)/128,1,2),128>>>(HW,l);
    }

    void *pk0,*pk1,*pv0,*pv1,*pt,*pf0,*pf1,*pfv0,*pfv1;
    cudaGetSymbolAddress(&pk0,g_k0);  cudaGetSymbolAddress(&pk1,g_k1);
    cudaGetSymbolAddress(&pv0,g_v0);  cudaGetSymbolAddress(&pv1,g_v1);
    cudaGetSymbolAddress(&pt,g_tmp);
    cudaGetSymbolAddress(&pf0,g_f0);  cudaGetSymbolAddress(&pf1,g_f1);
    cudaGetSymbolAddress(&pfv0,g_fv0); cudaGetSymbolAddress(&pfv1,g_fv1);

    size_t tb=0;
    cub::DeviceRadixSort::SortPairs(nullptr,tb,
        (const unsigned long long*)pk0,(unsigned long long*)pk1,
        (const unsigned*)pv0,(unsigned*)pv1,TALL,0,36);
    if(tb>sizeof(g_tmp)) return;
    size_t tcap=sizeof(g_tmp);
    cub::DeviceRadixSort::SortPairs(pt,tcap,
        (const unsigned long long*)pk0,(unsigned long long*)pk1,
        (const unsigned*)pv0,(unsigned*)pv1,TALL,0,36);

    decode_k<<<(60000+255)/256,256>>>(ih,iw);
    mask_k<<<dim3(MAXW,MAXW,10),64>>>();
    scan_k<<<10,128>>>();

    size_t tcap2=sizeof(g_tmp);
    cub::DeviceRadixSort::SortPairs(pt,tcap2,
        (const unsigned long long*)pf0,(unsigned long long*)pf1,
        (const unsigned*)pfv0,(unsigned*)pfv1,10000,0,33);

    out_k<<<8,256>>>((float*)d_out);
}

// round 9
// speedup vs baseline: 2.6636x; 1.3682x over previous
#include <cuda_runtime.h>
#include <cub/cub.cuh>
#include <math.h>

#define NEGF (-1000000000.0f)
#define TPI 218240
#define TALL 436480
#define MAXW 94
#define PXTOT 54560

__constant__ int dWl[5]={256,128,64,32,16};
__constant__ int dHl[5]={160,80,40,20,10};
__constant__ int dStr[5]={4,8,16,32,64};
__constant__ int dSz[5]={32,64,128,256,512};
__constant__ int dOff[5]={0,163840,204800,215040,217600};
__constant__ int dK[5]={6000,6000,6000,2560,640};
__constant__ int dPfx[5]={0,320,400,420,425};      // tile-block prefix per level
__constant__ int dPOff[5]={0,40960,51200,53760,54400}; // pixel offset per level in g_t
__constant__ double dRatio[4]={0.2323283,0.63365731,1.28478321,3.15089189};

__device__ float g_t[(size_t)2*256*PXTOT];      // conv output, all levels resident
__device__ float g_wT[9*256*256];               // conv w transposed [tap][ic][oc]
__device__ float g_wh[256*20];                  // fused head weights [ic][20]
__device__ float g_hb[20];
__device__ double g_anch[20*2];                 // per (l,a): wsd,hsd in f64
__device__ float g_obj[TALL];
__device__ float g_reg[(size_t)TALL*4];
__device__ unsigned long long g_k0[TALL], g_k1[TALL];
__device__ unsigned g_v0[TALL], g_v1[TALL];
__device__ float g_tb[10*6000*4];
__device__ float g_ts[10*6000];
__device__ float g_ta[10*6000];
__device__ unsigned long long g_mask[(size_t)10*6000*MAXW];
__device__ float g_ab[10000*4];
__device__ float g_as[10000];
__device__ unsigned long long g_f0[10000], g_f1[10000];
__device__ unsigned g_fv0[10000], g_fv1[10000];
__device__ __align__(256) unsigned char g_tmp[32u*1024u*1024u];

__device__ __forceinline__ unsigned sortable_f32(float f){
    unsigned u=__float_as_uint(f);
    return (u&0x80000000u)?~u:(u|0x80000000u);
}
__device__ __forceinline__ unsigned long long pk2(float x,float y){
    unsigned long long r;
    asm("mov.b64 %0,{%1,%2};":"=l"(r):"r"(__float_as_uint(x)),"r"(__float_as_uint(y)));
    return r;
}
__device__ __forceinline__ void fma2(unsigned long long&d,unsigned long long a,unsigned long long b){
    asm("fma.rn.f32x2 %0,%1,%2,%0;":"+l"(d):"l"(a),"l"(b));
}
__device__ __forceinline__ float2 up2(unsigned long long v){
    unsigned lo,hi; asm("mov.b64 {%0,%1},%2;":"=r"(lo),"=r"(hi):"l"(v));
    return make_float2(__uint_as_float(lo),__uint_as_float(hi));
}

// ---------- prep: transpose conv weights, fuse head weights, anchor table ----------
__global__ void prep_k(const float* __restrict__ cw,const float* __restrict__ clsw,
                       const float* __restrict__ bbw,const float* __restrict__ clsb,
                       const float* __restrict__ bbb){
    int i=blockIdx.x*blockDim.x+threadIdx.x;
    if(i<9*256*256){
        int tap=i/65536, r=i-tap*65536, ic=r>>8, oc=r&255;
        g_wT[i]=cw[(oc*256+ic)*9+tap];
    }
    if(i<256*20){
        int ic=i/20, o=i-ic*20;
        g_wh[i]=(o<4)?clsw[o*256+ic]:bbw[(o-4)*256+ic];
    }
    if(i<20) g_hb[i]=(i<4)?clsb[i]:bbb[i-4];
    if(i<20){
        int l=i/4, a=i-l*4;
        double sz=(double)dSz[l], rt=dRatio[a];
        double wsd=sqrt(sz*sz/rt);
        g_anch[i*2]=wsd; g_anch[i*2+1]=wsd*rt;
    }
}

// ---------- conv3x3+bias+ReLU over ALL levels in one launch ----------
// 128oc x 128px per block; round-5 balanced inner loop (float A smem + reg pk2).
__global__ void __launch_bounds__(256,2) conv_all_k(
        const float* __restrict__ f0,const float* __restrict__ f1,
        const float* __restrict__ f2,const float* __restrict__ f3,
        const float* __restrict__ f4,const float* __restrict__ bias){
    int t=blockIdx.x;
    int l=0;
#pragma unroll
    for(int q=1;q<5;q++) if(t>=dPfx[q]) l=q;
    const int H=dHl[l], W=dWl[l], HW=H*W;
    const int tileP=(t-dPfx[l])*128;
    const int ocB=blockIdx.y*128, b=blockIdx.z;
    const float* lf=(l==0)?f0:(l==1)?f1:(l==2)?f2:(l==3)?f3:f4;
    const float* __restrict__ inB=lf+(size_t)b*256*HW;
    float* __restrict__ outB=g_t+(size_t)b*256*PXTOT+dPOff[l];

    __shared__ float As[2][8][128];
    __shared__ float Bs[2][8][128];
    __shared__ int sIdx[9][128];
    const int tid=threadIdx.x, tx=tid&15, ty=tid>>4;

    for(int idx=tid;idx<9*128;idx+=256){
        int tap=idx>>7, p=idx&127, g=tileP+p, s=-1;
        if(g<HW){
            int y=g/W, x=g-y*W;
            int yy=y+tap/3-1, xx=x+(tap-(tap/3)*3)-1;
            if(yy>=0&&yy<H&&xx>=0&&xx<W) s=yy*W+xx;
        }
        sIdx[tap][p]=s;
    }
    __syncthreads();

    unsigned long long acc[8][4];
#pragma unroll
    for(int i=0;i<8;i++)
#pragma unroll
        for(int j=0;j<4;j++) acc[i][j]=0ull;

    float ra[4],rb[4];
    {
        const int* sI=sIdx[0];
#pragma unroll
        for(int j=0;j<4;j++){
            int idx=tid+(j<<8), k=idx>>7, q=idx&127;
            ra[j]=g_wT[(size_t)k*256+ocB+q];
            int s=sI[q]; rb[j]=(s>=0)?inB[(size_t)k*HW+s]:0.f;
        }
#pragma unroll
        for(int j=0;j<4;j++){
            int idx=tid+(j<<8), k=idx>>7, q=idx&127;
            As[0][k][q]=ra[j]; Bs[0][k][q]=rb[j];
        }
        __syncthreads();
    }

    for(int c=0;c<288;c++){
        int buf=c&1; bool pf=(c+1<288);
        if(pf){
            int cn=c+1, tap=cn>>5, icc=(cn&31)<<3;
            const int* sI=sIdx[tap];
#pragma unroll
            for(int j=0;j<4;j++){
                int idx=tid+(j<<8), k=idx>>7, q=idx&127;
                ra[j]=g_wT[((size_t)(tap<<8)+icc+k)*256+ocB+q];
                int s=sI[q]; rb[j]=(s>=0)?inB[(size_t)(icc+k)*HW+s]:0.f;
            }
        }
#pragma unroll
        for(int k=0;k<8;k++){
            float4 a0=*(const float4*)&As[buf][k][ty*4];
            float4 a1=*(const float4*)&As[buf][k][64+ty*4];
            float4 b0=*(const float4*)&Bs[buf][k][tx*4];
            float4 b1=*(const float4*)&Bs[buf][k][64+tx*4];
            unsigned long long bv[4];
            bv[0]=pk2(b0.x,b0.y); bv[1]=pk2(b0.z,b0.w);
            bv[2]=pk2(b1.x,b1.y); bv[3]=pk2(b1.z,b1.w);
            float av[8]={a0.x,a0.y,a0.z,a0.w,a1.x,a1.y,a1.z,a1.w};
#pragma unroll
            for(int i=0;i<8;i++){
                unsigned long long ai=pk2(av[i],av[i]);
#pragma unroll
                for(int j=0;j<4;j++) fma2(acc[i][j],ai,bv[j]);
            }
        }
        if(pf){
            int nb=buf^1;
#pragma unroll
            for(int j=0;j<4;j++){
                int idx=tid+(j<<8), k=idx>>7, q=idx&127;
                As[nb][k][q]=ra[j]; Bs[nb][k][q]=rb[j];
            }
        }
        __syncthreads();
    }

#pragma unroll
    for(int i=0;i<8;i++){
        int oc=ocB+((i<4)?(ty*4+i):(64+ty*4+i-4));
        float bv=bias[oc];
        float* row=outB+(size_t)oc*PXTOT;
        float2 v0=up2(acc[i][0]), v1=up2(acc[i][1]);
        float2 v2=up2(acc[i][2]), v3=up2(acc[i][3]);
        int p0=tileP+tx*4;
        if(p0<HW){
            float4 v; v.x=fmaxf(v0.x+bv,0.f); v.y=fmaxf(v0.y+bv,0.f);
            v.z=fmaxf(v1.x+bv,0.f); v.w=fmaxf(v1.y+bv,0.f);
            *(float4*)&row[p0]=v;
        }
        int p1=tileP+64+tx*4;
        if(p1<HW){
            float4 v; v.x=fmaxf(v2.x+bv,0.f); v.y=fmaxf(v2.y+bv,0.f);
            v.z=fmaxf(v3.x+bv,0.f); v.w=fmaxf(v3.y+bv,0.f);
            *(float4*)&row[p1]=v;
        }
    }
}

// ---------- fused 1x1 heads over ALL levels in one launch ----------
__global__ void head_all_k(){
    __shared__ float ws[256*20];
    __shared__ float wb[20];
    int tid=threadIdx.x;
    for(int i=tid;i<5120;i+=128) ws[i]=g_wh[i];
    if(tid<20) wb[tid]=g_hb[tid];
    __syncthreads();
    int t=blockIdx.x;
    int l=0;
#pragma unroll
    for(int q=1;q<5;q++) if(t>=dPfx[q]) l=q;
    int HW=dHl[l]*dWl[l];
    int px=(t-dPfx[l])*128+tid;
    int b=blockIdx.z;
    if(px>=HW) return;
    const float* tb=g_t+(size_t)b*256*PXTOT+dPOff[l]+px;
    float acc[20];
#pragma unroll
    for(int o=0;o<20;o++) acc[o]=wb[o];
#pragma unroll 4
    for(int ic=0;ic<256;ic++){
        float x=__ldg(&tb[(size_t)ic*PXTOT]);
        const float* w=&ws[ic*20];
#pragma unroll
        for(int o=0;o<20;o++) acc[o]+=x*w[o];
    }
    size_t base=(size_t)b*TPI+dOff[l]+(size_t)px*4;
    int seg=b*5+l;
#pragma unroll
    for(int a=0;a<4;a++){
        float lg=acc[a];
        g_obj[base+a]=lg;
        unsigned u=sortable_f32(lg);
        g_k0[base+a]=((unsigned long long)seg<<32)|(unsigned long long)(unsigned)(~u);
        g_v0[base+a]=(unsigned)(px*4+a);
#pragma unroll
        for(int cc=0;cc<4;cc++) g_reg[(base+a)*4+cc]=acc[4+a*4+cc];
    }
}

// ---------- per-(b,l) top-k decode + clip (bit-faithful elementwise) ----------
__global__ void decode_k(const int* __restrict__ ihp,const int* __restrict__ iwp){
    int id=blockIdx.x*blockDim.x+threadIdx.x;
    if(id>=60000) return;
    int s=id/6000, i=id-s*6000, b=s/5, l=s-b*5;
    if(i>=dK[l]) return;
    size_t base=(size_t)b*TPI+dOff[l];
    unsigned n=g_v1[base+i];
    int a=n&3, p=n>>2, W=dWl[l], y=p/W, x=p-y*W;
    double wsd=g_anch[(l*4+a)*2], hsd=g_anch[(l*4+a)*2+1];
    double gx=(double)(x*dStr[l]), gy=(double)(y*dStr[l]);
    float a0=(float)(gx-wsd*0.5), a1=(float)(gy-hsd*0.5);
    float a2=(float)(gx+wsd*0.5), a3=(float)(gy+hsd*0.5);
    const float* r=&g_reg[(base+n)*4];
    float dx=r[0],dy=r[1];
    float dw=fminf(r[2],4.135166556742356f), dh=fminf(r[3],4.135166556742356f);
    float wa=__fadd_rn(__fsub_rn(a2,a0),1.f), ha=__fadd_rn(__fsub_rn(a3,a1),1.f);
    float cxa=__fadd_rn(a0,__fmul_rn(0.5f,wa)), cya=__fadd_rn(a1,__fmul_rn(0.5f,ha));
    float cx=__fadd_rn(__fmul_rn(dx,wa),cxa), cy=__fadd_rn(__fmul_rn(dy,ha),cya);
    float w=__fmul_rn((float)exp((double)dw),wa), h=__fmul_rn((float)exp((double)dh),ha);
    float x1=__fsub_rn(cx,__fmul_rn(0.5f,w)), y1=__fsub_rn(cy,__fmul_rn(0.5f,h));
    float x2=__fsub_rn(__fadd_rn(cx,__fmul_rn(0.5f,w)),1.f);
    float y2=__fsub_rn(__fadd_rn(cy,__fmul_rn(0.5f,h)),1.f);
    float mw=(float)(*iwp)-1.f, mh=(float)(*ihp)-1.f;
    x1=fminf(fmaxf(x1,0.f),mw); x2=fminf(fmaxf(x2,0.f),mw);
    y1=fminf(fmaxf(y1,0.f),mh); y2=fminf(fmaxf(y2,0.f),mh);
    float* ob=&g_tb[(size_t)(s*6000+i)*4];
    ob[0]=x1; ob[1]=y1; ob[2]=x2; ob[3]=y2;
    g_ta[s*6000+i]=__fmul_rn(__fsub_rn(x2,x1),__fsub_rn(y2,y1));
    float lg=g_obj[base+n];
    g_ts[s*6000+i]=(float)(1.0/(1.0+exp(-(double)lg)));
}

// ---------- NMS phase 1: pairwise suppression bitmap ----------
__global__ void mask_k(){
    int s=blockIdx.z;
    int rowB=blockIdx.y, colB=blockIdx.x;
    int l=s%5; int k=dK[l];
    if(rowB*64>=k || colB<rowB || colB*64>=k) return;
    __shared__ float cb[64*5];
    int tid=threadIdx.x;   // 64
    const float* bx=&g_tb[(size_t)s*6000*4];
    const float* ar=&g_ta[(size_t)s*6000];
    int j0=colB*64;
    if(j0+tid<k){
        cb[tid*5+0]=bx[(j0+tid)*4+0];
        cb[tid*5+1]=bx[(j0+tid)*4+1];
        cb[tid*5+2]=bx[(j0+tid)*4+2];
        cb[tid*5+3]=bx[(j0+tid)*4+3];
        cb[tid*5+4]=ar[j0+tid];
    }
    __syncthreads();
    int i=rowB*64+tid;
    if(i>=k) return;
    float b0=bx[i*4],b1=bx[i*4+1],b2=bx[i*4+2],b3=bx[i*4+3],ba=ar[i];
    unsigned long long m=0;
    int jmax=min(64,k-j0);
    for(int t=0;t<jmax;t++){
        int j=j0+t;
        if(j<=i) continue;
        float xx1=fmaxf(b0,cb[t*5+0]), yy1=fmaxf(b1,cb[t*5+1]);
        float xx2=fminf(b2,cb[t*5+2]), yy2=fminf(b3,cb[t*5+3]);
        float inter=__fmul_rn(fmaxf(__fsub_rn(xx2,xx1),0.f),
                              fmaxf(__fsub_rn(yy2,yy1),0.f));
        float den=__fadd_rn(__fsub_rn(__fadd_rn(ba,cb[t*5+4]),inter),1e-9f);
        if(__fdiv_rn(inter,den)>0.7f) m|=(1ull<<t);
    }
    g_mask[((size_t)s*6000+i)*MAXW+colB]=m;
}

// ---------- NMS phase 2: 1-warp greedy scan + output ----------
__global__ void scan_k(){
    int s=blockIdx.x; int b=s/5, l=s-b*5;
    int k=dK[l], n_out=min(1000,k);
    __shared__ int keep[1000];
    int tid=threadIdx.x;   // 128
    for(int j=tid;j<1000;j+=128) keep[j]=-1;
    __syncthreads();
    if(tid<32){
        unsigned long long rem0=0,rem1=0,rem2=0;
        const unsigned long long* MR=&g_mask[(size_t)s*6000*MAXW];
        int nw=(k+63)>>6;
        int nk=0;
        for(int i=0;i<k && nk<n_out;i++){
            int w=i>>6, slot=w>>5, lane=w&31;
            unsigned long long v=(slot==0)?rem0:((slot==1)?rem1:rem2);
            unsigned long long rw=__shfl_sync(0xffffffffu,v,lane);
            if((rw>>(i&63))&1ull) continue;
            if(tid==0) keep[nk]=i;
            nk++;
            const unsigned long long* row=MR+(size_t)i*MAXW;
            int w0=tid, w1=tid+32, w2=tid+64;
            if(w0<nw && w0>=w) rem0|=row[w0];
            if(w1<nw && w1>=w) rem1|=row[w1];
            if(w2<nw && w2>=w) rem2|=row[w2];
        }
    }
    __syncthreads();
    const float* bx=&g_tb[(size_t)s*6000*4];
    for(int j=tid;j<1000;j+=128){
        int gi=b*5000+l*1000+j;
        float B0=0.f,B1=0.f,B2=0.f,B3=0.f,S=NEGF;
        if(j<n_out){
            int ki=keep[j];
            if(ki>=0){
                B0=bx[ki*4];B1=bx[ki*4+1];B2=bx[ki*4+2];B3=bx[ki*4+3];
                S=g_ts[s*6000+ki];
            } else { B0=bx[0];B1=bx[1];B2=bx[2];B3=bx[3]; S=NEGF; }
        }
        g_ab[(size_t)gi*4]=B0; g_ab[(size_t)gi*4+1]=B1;
        g_ab[(size_t)gi*4+2]=B2; g_ab[(size_t)gi*4+3]=B3;
        g_as[gi]=S;
        unsigned u=sortable_f32(S);
        g_f0[gi]=((unsigned long long)b<<32)|(unsigned long long)(unsigned)(~u);
        g_fv0[gi]=(unsigned)(l*1000+j);
    }
}

// ---------- final gather ----------
__global__ void out_k(float* __restrict__ out){
    int id=blockIdx.x*blockDim.x+threadIdx.x;
    if(id>=2000) return;
    int b=id/1000, r=id-b*1000;
    unsigned idx=g_fv1[b*5000+r];
    float* o=&out[(size_t)(b*1000+r)*5];
    const float* bb=&g_ab[((size_t)b*5000+idx)*4];
    o[0]=bb[0]; o[1]=bb[1]; o[2]=bb[2]; o[3]=bb[3];
    o[4]=g_as[b*5000+idx];
}

extern "C" void kernel_launch(void* const* d_in,const int* in_sizes,int n_in,
                              void* d_out,int out_size){
    const float* f0=(const float*)d_in[0];
    const float* f1=(const float*)d_in[1];
    const float* f2=(const float*)d_in[2];
    const float* f3=(const float*)d_in[3];
    const float* f4=(const float*)d_in[4];
    const float* conv_w=(const float*)d_in[5];
    const float* conv_b=(const float*)d_in[6];
    const float* cls_w =(const float*)d_in[7];
    const float* cls_b =(const float*)d_in[8];
    const float* bbox_w=(const float*)d_in[9];
    const float* bbox_b=(const float*)d_in[10];
    const int* ih=(const int*)d_in[11];
    const int* iw=(const int*)d_in[12];

    prep_k<<<2304,256>>>(conv_w,cls_w,bbox_w,cls_b,bbox_b);

    conv_all_k<<<dim3(427,2,2),256>>>(f0,f1,f2,f3,f4,conv_b);
    head_all_k<<<dim3(427,1,2),128>>>();

    void *pk0,*pk1,*pv0,*pv1,*pt,*pf0,*pf1,*pfv0,*pfv1;
    cudaGetSymbolAddress(&pk0,g_k0);  cudaGetSymbolAddress(&pk1,g_k1);
    cudaGetSymbolAddress(&pv0,g_v0);  cudaGetSymbolAddress(&pv1,g_v1);
    cudaGetSymbolAddress(&pt,g_tmp);
    cudaGetSymbolAddress(&pf0,g_f0);  cudaGetSymbolAddress(&pf1,g_f1);
    cudaGetSymbolAddress(&pfv0,g_fv0); cudaGetSymbolAddress(&pfv1,g_fv1);

    size_t tb=0;
    cub::DeviceRadixSort::SortPairs(nullptr,tb,
        (const unsigned long long*)pk0,(unsigned long long*)pk1,
        (const unsigned*)pv0,(unsigned*)pv1,TALL,0,36);
    if(tb>sizeof(g_tmp)) return;
    size_t tcap=sizeof(g_tmp);
    cub::DeviceRadixSort::SortPairs(pt,tcap,
        (const unsigned long long*)pk0,(unsigned long long*)pk1,
        (const unsigned*)pv0,(unsigned*)pv1,TALL,0,36);

    decode_k<<<(60000+255)/256,256>>>(ih,iw);
    mask_k<<<dim3(MAXW,MAXW,10),64>>>();
    scan_k<<<10,128>>>();

    size_t tcap2=sizeof(g_tmp);
    cub::DeviceRadixSort::SortPairs(pt,tcap2,
        (const unsigned long long*)pf0,(unsigned long long*)pf1,
        (const unsigned*)pfv0,(unsigned*)pfv1,10000,0,33);

    out_k<<<8,256>>>((float*)d_out);
}

// round 12
// speedup vs baseline: 2.9375x; 1.1028x over previous
#include <cuda_runtime.h>
#include <cub/cub.cuh>
#include <math.h>

#define NEGF (-1000000000.0f)
#define TPI 218240
#define TALL 436480
#define MAXW 94
#define PXTOT 54560

__constant__ int dWl[5]={256,128,64,32,16};
__constant__ int dHl[5]={160,80,40,20,10};
__constant__ int dStr[5]={4,8,16,32,64};
__constant__ int dSz[5]={32,64,128,256,512};
__constant__ int dOff[5]={0,163840,204800,215040,217600};
__constant__ int dK[5]={6000,6000,6000,2560,640};
__constant__ int dPfx[5]={0,320,400,420,425};
__constant__ int dPOff[5]={0,40960,51200,53760,54400};
__constant__ double dRatio[4]={0.2323283,0.63365731,1.28478321,3.15089189};

__device__ float g_t[(size_t)2*256*PXTOT];
__device__ float g_wT[9*256*256];
__device__ float g_wh[256*20];
__device__ float g_hb[20];
__device__ double g_anch[20*2];
__device__ float g_obj[TALL];
__device__ float g_reg[(size_t)TALL*4];
__device__ unsigned long long g_k0[TALL], g_k1[TALL];
__device__ unsigned g_v0[TALL], g_v1[TALL];
__device__ float g_tb[10*6000*4];
__device__ float g_ts[10*6000];
__device__ float g_ta[10*6000];
__device__ unsigned long long g_mask[(size_t)10*6000*MAXW];
__device__ float g_ab[10000*4];
__device__ float g_as[10000];
__device__ unsigned long long g_f0[10000], g_f1[10000];
__device__ unsigned g_fv0[10000], g_fv1[10000];
__device__ __align__(256) unsigned char g_tmp[32u*1024u*1024u];

__device__ __forceinline__ unsigned sortable_f32(float f){
    unsigned u=__float_as_uint(f);
    return (u&0x80000000u)?~u:(u|0x80000000u);
}
__device__ __forceinline__ unsigned long long pk2(float x,float y){
    unsigned long long r;
    asm("mov.b64 %0,{%1,%2};":"=l"(r):"r"(__float_as_uint(x)),"r"(__float_as_uint(y)));
    return r;
}
__device__ __forceinline__ void fma2(unsigned long long&d,unsigned long long a,unsigned long long b){
    asm("fma.rn.f32x2 %0,%1,%2,%0;":"+l"(d):"l"(a),"l"(b));
}
__device__ __forceinline__ float2 up2(unsigned long long v){
    unsigned lo,hi; asm("mov.b64 {%0,%1},%2;":"=r"(lo),"=r"(hi):"l"(v));
    return make_float2(__uint_as_float(lo),__uint_as_float(hi));
}

// ---------- prep: transpose conv weights, fuse head weights, anchor table ----------
__global__ void prep_k(const float* __restrict__ cw,const float* __restrict__ clsw,
                       const float* __restrict__ bbw,const float* __restrict__ clsb,
                       const float* __restrict__ bbb){
    int i=blockIdx.x*blockDim.x+threadIdx.x;
    if(i<9*256*256){
        int tap=i/65536, r=i-tap*65536, ic=r>>8, oc=r&255;
        g_wT[i]=cw[(oc*256+ic)*9+tap];
    }
    if(i<256*20){
        int ic=i/20, o=i-ic*20;
        g_wh[i]=(o<4)?clsw[o*256+ic]:bbw[(o-4)*256+ic];
    }
    if(i<20) g_hb[i]=(i<4)?clsb[i]:bbb[i-4];
    if(i<20){
        int l=i/4, a=i-l*4;
        double sz=(double)dSz[l], rt=dRatio[a];
        double wsd=sqrt(sz*sz/rt);
        g_anch[i*2]=wsd; g_anch[i*2+1]=wsd*rt;
    }
}

// ---------- conv3x3+bias+ReLU over ALL levels in one launch (round-9 proven form) ----------
__global__ void __launch_bounds__(256,2) conv_all_k(
        const float* __restrict__ f0,const float* __restrict__ f1,
        const float* __restrict__ f2,const float* __restrict__ f3,
        const float* __restrict__ f4,const float* __restrict__ bias){
    int t=blockIdx.x;
    int l=0;
#pragma unroll
    for(int q=1;q<5;q++) if(t>=dPfx[q]) l=q;
    const int H=dHl[l], W=dWl[l], HW=H*W;
    const int tileP=(t-dPfx[l])*128;
    const int ocB=blockIdx.y*128, b=blockIdx.z;
    const float* lf=(l==0)?f0:(l==1)?f1:(l==2)?f2:(l==3)?f3:f4;
    const float* __restrict__ inB=lf+(size_t)b*256*HW;
    float* __restrict__ outB=g_t+(size_t)b*256*PXTOT+dPOff[l];

    __shared__ float As[2][8][128];
    __shared__ float Bs[2][8][128];
    __shared__ int sIdx[9][128];
    const int tid=threadIdx.x, tx=tid&15, ty=tid>>4;

    for(int idx=tid;idx<9*128;idx+=256){
        int tap=idx>>7, p=idx&127, g=tileP+p, s=-1;
        if(g<HW){
            int y=g/W, x=g-y*W;
            int yy=y+tap/3-1, xx=x+(tap-(tap/3)*3)-1;
            if(yy>=0&&yy<H&&xx>=0&&xx<W) s=yy*W+xx;
        }
        sIdx[tap][p]=s;
    }
    __syncthreads();

    unsigned long long acc[8][4];
#pragma unroll
    for(int i=0;i<8;i++)
#pragma unroll
        for(int j=0;j<4;j++) acc[i][j]=0ull;

    float ra[4],rb[4];
    {
        const int* sI=sIdx[0];
#pragma unroll
        for(int j=0;j<4;j++){
            int idx=tid+(j<<8), k=idx>>7, q=idx&127;
            ra[j]=g_wT[(size_t)k*256+ocB+q];
            int s=sI[q]; rb[j]=(s>=0)?inB[(size_t)k*HW+s]:0.f;
        }
#pragma unroll
        for(int j=0;j<4;j++){
            int idx=tid+(j<<8), k=idx>>7, q=idx&127;
            As[0][k][q]=ra[j]; Bs[0][k][q]=rb[j];
        }
        __syncthreads();
    }

    for(int c=0;c<288;c++){
        int buf=c&1; bool pf=(c+1<288);
        if(pf){
            int cn=c+1, tap=cn>>5, icc=(cn&31)<<3;
            const int* sI=sIdx[tap];
#pragma unroll
            for(int j=0;j<4;j++){
                int idx=tid+(j<<8), k=idx>>7, q=idx&127;
                ra[j]=g_wT[((size_t)(tap<<8)+icc+k)*256+ocB+q];
                int s=sI[q]; rb[j]=(s>=0)?inB[(size_t)(icc+k)*HW+s]:0.f;
            }
        }
#pragma unroll
        for(int k=0;k<8;k++){
            float4 a0=*(const float4*)&As[buf][k][ty*4];
            float4 a1=*(const float4*)&As[buf][k][64+ty*4];
            float4 b0=*(const float4*)&Bs[buf][k][tx*4];
            float4 b1=*(const float4*)&Bs[buf][k][64+tx*4];
            unsigned long long bv[4];
            bv[0]=pk2(b0.x,b0.y); bv[1]=pk2(b0.z,b0.w);
            bv[2]=pk2(b1.x,b1.y); bv[3]=pk2(b1.z,b1.w);
            float av[8]={a0.x,a0.y,a0.z,a0.w,a1.x,a1.y,a1.z,a1.w};
#pragma unroll
            for(int i=0;i<8;i++){
                unsigned long long ai=pk2(av[i],av[i]);
#pragma unroll
                for(int j=0;j<4;j++) fma2(acc[i][j],ai,bv[j]);
            }
        }
        if(pf){
            int nb=buf^1;
#pragma unroll
            for(int j=0;j<4;j++){
                int idx=tid+(j<<8), k=idx>>7, q=idx&127;
                As[nb][k][q]=ra[j]; Bs[nb][k][q]=rb[j];
            }
        }
        __syncthreads();
    }

#pragma unroll
    for(int i=0;i<8;i++){
        int oc=ocB+((i<4)?(ty*4+i):(64+ty*4+i-4));
        float bv=bias[oc];
        float* row=outB+(size_t)oc*PXTOT;
        float2 v0=up2(acc[i][0]), v1=up2(acc[i][1]);
        float2 v2=up2(acc[i][2]), v3=up2(acc[i][3]);
        int p0=tileP+tx*4;
        if(p0<HW){
            float4 v; v.x=fmaxf(v0.x+bv,0.f); v.y=fmaxf(v0.y+bv,0.f);
            v.z=fmaxf(v1.x+bv,0.f); v.w=fmaxf(v1.y+bv,0.f);
            *(float4*)&row[p0]=v;
        }
        int p1=tileP+64+tx*4;
        if(p1<HW){
            float4 v; v.x=fmaxf(v2.x+bv,0.f); v.y=fmaxf(v2.y+bv,0.f);
            v.z=fmaxf(v3.x+bv,0.f); v.w=fmaxf(v3.y+bv,0.f);
            *(float4*)&row[p1]=v;
        }
    }
}

// ---------- fused 1x1 heads over all levels ----------
__global__ void head_all_k(){
    __shared__ float ws[256*20];
    __shared__ float wb[20];
    int tid=threadIdx.x;
    for(int i=tid;i<5120;i+=128) ws[i]=g_wh[i];
    if(tid<20) wb[tid]=g_hb[tid];
    __syncthreads();
    int t=blockIdx.x;
    int l=0;
#pragma unroll
    for(int q=1;q<5;q++) if(t>=dPfx[q]) l=q;
    int HW=dHl[l]*dWl[l];
    int px=(t-dPfx[l])*128+tid;
    int b=blockIdx.z;
    if(px>=HW) return;
    const float* tb=g_t+(size_t)b*256*PXTOT+dPOff[l]+px;
    float acc[20];
#pragma unroll
    for(int o=0;o<20;o++) acc[o]=wb[o];
#pragma unroll 4
    for(int ic=0;ic<256;ic++){
        float x=__ldg(&tb[(size_t)ic*PXTOT]);
        const float* w=&ws[ic*20];
#pragma unroll
        for(int o=0;o<20;o++) acc[o]+=x*w[o];
    }
    size_t base=(size_t)b*TPI+dOff[l]+(size_t)px*4;
    int seg=b*5+l;
#pragma unroll
    for(int a=0;a<4;a++){
        float lg=acc[a];
        g_obj[base+a]=lg;
        unsigned u=sortable_f32(lg);
        g_k0[base+a]=((unsigned long long)seg<<32)|(unsigned long long)(unsigned)(~u);
        g_v0[base+a]=(unsigned)(px*4+a);
#pragma unroll
        for(int cc=0;cc<4;cc++) g_reg[(base+a)*4+cc]=acc[4+a*4+cc];
    }
}

// ---------- per-(b,l) top-k decode + clip ----------
__global__ void decode_k(const int* __restrict__ ihp,const int* __restrict__ iwp){
    int id=blockIdx.x*blockDim.x+threadIdx.x;
    if(id>=60000) return;
    int s=id/6000, i=id-s*6000, b=s/5, l=s-b*5;
    if(i>=dK[l]) return;
    size_t base=(size_t)b*TPI+dOff[l];
    unsigned n=g_v1[base+i];
    int a=n&3, p=n>>2, W=dWl[l], y=p/W, x=p-y*W;
    double wsd=g_anch[(l*4+a)*2], hsd=g_anch[(l*4+a)*2+1];
    double gx=(double)(x*dStr[l]), gy=(double)(y*dStr[l]);
    float a0=(float)(gx-wsd*0.5), a1=(float)(gy-hsd*0.5);
    float a2=(float)(gx+wsd*0.5), a3=(float)(gy+hsd*0.5);
    const float* r=&g_reg[(base+n)*4];
    float dx=r[0],dy=r[1];
    float dw=fminf(r[2],4.135166556742356f), dh=fminf(r[3],4.135166556742356f);
    float wa=__fadd_rn(__fsub_rn(a2,a0),1.f), ha=__fadd_rn(__fsub_rn(a3,a1),1.f);
    float cxa=__fadd_rn(a0,__fmul_rn(0.5f,wa)), cya=__fadd_rn(a1,__fmul_rn(0.5f,ha));
    float cx=__fadd_rn(__fmul_rn(dx,wa),cxa), cy=__fadd_rn(__fmul_rn(dy,ha),cya);
    float w=__fmul_rn((float)exp((double)dw),wa), h=__fmul_rn((float)exp((double)dh),ha);
    float x1=__fsub_rn(cx,__fmul_rn(0.5f,w)), y1=__fsub_rn(cy,__fmul_rn(0.5f,h));
    float x2=__fsub_rn(__fadd_rn(cx,__fmul_rn(0.5f,w)),1.f);
    float y2=__fsub_rn(__fadd_rn(cy,__fmul_rn(0.5f,h)),1.f);
    float mw=(float)(*iwp)-1.f, mh=(float)(*ihp)-1.f;
    x1=fminf(fmaxf(x1,0.f),mw); x2=fminf(fmaxf(x2,0.f),mw);
    y1=fminf(fmaxf(y1,0.f),mh); y2=fminf(fmaxf(y2,0.f),mh);
    float* ob=&g_tb[(size_t)(s*6000+i)*4];
    ob[0]=x1; ob[1]=y1; ob[2]=x2; ob[3]=y2;
    g_ta[s*6000+i]=__fmul_rn(__fsub_rn(x2,x1),__fsub_rn(y2,y1));
    float lg=g_obj[base+n];
    g_ts[s*6000+i]=(float)(1.0/(1.0+exp(-(double)lg)));
}

// ---------- NMS phase 1: bitmap, exact-decision division screen ----------
// inter*4 is exact (pow2 scale). inter*4 < den  =>  ratio < 0.25  =>
// fl(inter/den) <= 0.25*(1+eps) < 0.7: identical decision without the div.
__global__ void mask_k(){
    int s=blockIdx.z;
    int rowB=blockIdx.y, colB=blockIdx.x;
    int l=s%5; int k=dK[l];
    if(rowB*64>=k || colB<rowB || colB*64>=k) return;
    __shared__ float cb[64*5];
    int tid=threadIdx.x;   // 64
    const float* bx=&g_tb[(size_t)s*6000*4];
    const float* ar=&g_ta[(size_t)s*6000];
    int j0=colB*64;
    if(j0+tid<k){
        cb[tid*5+0]=bx[(j0+tid)*4+0];
        cb[tid*5+1]=bx[(j0+tid)*4+1];
        cb[tid*5+2]=bx[(j0+tid)*4+2];
        cb[tid*5+3]=bx[(j0+tid)*4+3];
        cb[tid*5+4]=ar[j0+tid];
    }
    __syncthreads();
    int i=rowB*64+tid;
    if(i>=k) return;
    float b0=bx[i*4],b1=bx[i*4+1],b2=bx[i*4+2],b3=bx[i*4+3],ba=ar[i];
    unsigned long long m=0;
    int jmax=min(64,k-j0);
    for(int t=0;t<jmax;t++){
        int j=j0+t;
        if(j<=i) continue;
        float xx1=fmaxf(b0,cb[t*5+0]), yy1=fmaxf(b1,cb[t*5+1]);
        float xx2=fminf(b2,cb[t*5+2]), yy2=fminf(b3,cb[t*5+3]);
        float inter=__fmul_rn(fmaxf(__fsub_rn(xx2,xx1),0.f),
                              fmaxf(__fsub_rn(yy2,yy1),0.f));
        float den=__fadd_rn(__fsub_rn(__fadd_rn(ba,cb[t*5+4]),inter),1e-9f);
        if(__fmul_rn(inter,4.0f)>=den){
            if(__fdiv_rn(inter,den)>0.7f) m|=(1ull<<t);
        }
    }
    g_mask[((size_t)s*6000+i)*MAXW+colB]=m;
}

// ---------- NMS phase 2: 1-warp greedy scan + output ----------
__global__ void scan_k(){
    int s=blockIdx.x; int b=s/5, l=s-b*5;
    int k=dK[l], n_out=min(1000,k);
    __shared__ int keep[1000];
    int tid=threadIdx.x;   // 128
    for(int j=tid;j<1000;j+=128) keep[j]=-1;
    __syncthreads();
    if(tid<32){
        unsigned long long rem0=0,rem1=0,rem2=0;
        const unsigned long long* MR=&g_mask[(size_t)s*6000*MAXW];
        int nw=(k+63)>>6;
        int nk=0;
        for(int i=0;i<k && nk<n_out;i++){
            int w=i>>6, slot=w>>5, lane=w&31;
            unsigned long long v=(slot==0)?rem0:((slot==1)?rem1:rem2);
            unsigned long long rw=__shfl_sync(0xffffffffu,v,lane);
            if((rw>>(i&63))&1ull) continue;
            if(tid==0) keep[nk]=i;
            nk++;
            const unsigned long long* row=MR+(size_t)i*MAXW;
            int w0=tid, w1=tid+32, w2=tid+64;
            if(w0<nw && w0>=w) rem0|=row[w0];
            if(w1<nw && w1>=w) rem1|=row[w1];
            if(w2<nw && w2>=w) rem2|=row[w2];
        }
    }
    __syncthreads();
    const float* bx=&g_tb[(size_t)s*6000*4];
    for(int j=tid;j<1000;j+=128){
        int gi=b*5000+l*1000+j;
        float B0=0.f,B1=0.f,B2=0.f,B3=0.f,S=NEGF;
        if(j<n_out){
            int ki=keep[j];
            if(ki>=0){
                B0=bx[ki*4];B1=bx[ki*4+1];B2=bx[ki*4+2];B3=bx[ki*4+3];
                S=g_ts[s*6000+ki];
            } else { B0=bx[0];B1=bx[1];B2=bx[2];B3=bx[3]; S=NEGF; }
        }
        g_ab[(size_t)gi*4]=B0; g_ab[(size_t)gi*4+1]=B1;
        g_ab[(size_t)gi*4+2]=B2; g_ab[(size_t)gi*4+3]=B3;
        g_as[gi]=S;
        unsigned u=sortable_f32(S);
        g_f0[gi]=((unsigned long long)b<<32)|(unsigned long long)(unsigned)(~u);
        g_fv0[gi]=(unsigned)(l*1000+j);
    }
}

// ---------- final gather ----------
__global__ void out_k(float* __restrict__ out){
    int id=blockIdx.x*blockDim.x+threadIdx.x;
    if(id>=2000) return;
    int b=id/1000, r=id-b*1000;
    unsigned idx=g_fv1[b*5000+r];
    float* o=&out[(size_t)(b*1000+r)*5];
    const float* bb=&g_ab[((size_t)b*5000+idx)*4];
    o[0]=bb[0]; o[1]=bb[1]; o[2]=bb[2]; o[3]=bb[3];
    o[4]=g_as[b*5000+idx];
}

extern "C" void kernel_launch(void* const* d_in,const int* in_sizes,int n_in,
                              void* d_out,int out_size){
    const float* f0=(const float*)d_in[0];
    const float* f1=(const float*)d_in[1];
    const float* f2=(const float*)d_in[2];
    const float* f3=(const float*)d_in[3];
    const float* f4=(const float*)d_in[4];
    const float* conv_w=(const float*)d_in[5];
    const float* conv_b=(const float*)d_in[6];
    const float* cls_w =(const float*)d_in[7];
    const float* cls_b =(const float*)d_in[8];
    const float* bbox_w=(const float*)d_in[9];
    const float* bbox_b=(const float*)d_in[10];
    const int* ih=(const int*)d_in[11];
    const int* iw=(const int*)d_in[12];

    prep_k<<<2304,256>>>(conv_w,cls_w,bbox_w,cls_b,bbox_b);

    conv_all_k<<<dim3(427,2,2),256>>>(f0,f1,f2,f3,f4,conv_b);
    head_all_k<<<dim3(427,1,2),128>>>();

    void *pk0,*pk1,*pv0,*pv1,*pt,*pf0,*pf1,*pfv0,*pfv1;
    cudaGetSymbolAddress(&pk0,g_k0);  cudaGetSymbolAddress(&pk1,g_k1);
    cudaGetSymbolAddress(&pv0,g_v0);  cudaGetSymbolAddress(&pv1,g_v1);
    cudaGetSymbolAddress(&pt,g_tmp);
    cudaGetSymbolAddress(&pf0,g_f0);  cudaGetSymbolAddress(&pf1,g_f1);
    cudaGetSymbolAddress(&pfv0,g_fv0); cudaGetSymbolAddress(&pfv1,g_fv1);

    size_t tb=0;
    cub::DeviceRadixSort::SortPairs(nullptr,tb,
        (const unsigned long long*)pk0,(unsigned long long*)pk1,
        (const unsigned*)pv0,(unsigned*)pv1,TALL,0,36);
    if(tb>sizeof(g_tmp)) return;
    size_t tcap=sizeof(g_tmp);
    cub::DeviceRadixSort::SortPairs(pt,tcap,
        (const unsigned long long*)pk0,(unsigned long long*)pk1,
        (const unsigned*)pv0,(unsigned*)pv1,TALL,0,36);

    decode_k<<<(60000+255)/256,256>>>(ih,iw);
    mask_k<<<dim3(MAXW,MAXW,10),64>>>();
    scan_k<<<10,128>>>();

    size_t tcap2=sizeof(g_tmp);
    cub::DeviceRadixSort::SortPairs(pt,tcap2,
        (const unsigned long long*)pf0,(unsigned long long*)pf1,
        (const unsigned*)pfv0,(unsigned*)pfv1,10000,0,33);

    out_k<<<8,256>>>((float*)d_out);
}